// round 2
// baseline (speedup 1.0000x reference)
#include <cuda_runtime.h>
#include <cstdint>

// Problem constants
#define NB   32
#define CIN  64
#define COUT 64
#define HH   160
#define WW   160
#define HW   (HH*WW)          // 25600
#define H2   162              // padded
#define W2   162
#define PADWORDS (NB*H2*W2)   // 839808

#define ZMAX 8192

// Scratch (device globals — no allocation allowed)
__device__ unsigned long long g_packed[PADWORDS];      // padded sign words, border = 0
__device__ unsigned long long g_pw[COUT*9];            // weight sign words per (co, tap)
__device__ float              g_alpha[COUT];
__device__ float2             g_coeff[9*COUT];         // per (boundary class, co): {alpha*(576-corr), -2*alpha}
__device__ int                g_zero_count;
__device__ int                g_zero_list[ZMAX];       // packed (b,ci,y,x,treated_sign)

// ---------------------------------------------------------------------------
// Kernel 1: weight prep. 1 block, 64 threads (one per co).
// ---------------------------------------------------------------------------
__global__ void prep_kernel(const float* __restrict__ w)
{
    int co = threadIdx.x;
    if (co == 0) g_zero_count = 0;   // reset fixup list every launch (runs before pack)
    if (co >= COUT) return;

    unsigned long long bits[9];
#pragma unroll
    for (int t = 0; t < 9; t++) bits[t] = 0ull;

    float sum = 0.0f;
    for (int ci = 0; ci < CIN; ci++) {
#pragma unroll
        for (int t = 0; t < 9; t++) {
            float v = w[(co*CIN + ci)*9 + t];
            float vc = fminf(fmaxf(v, -1.0f), 1.0f);
            sum += fabsf(vc);
            // sign bit: 1 == positive (exact zero treated as +; measure-zero for weights)
            if (!(__float_as_uint(vc) >> 31)) bits[t] |= (1ull << ci);
        }
    }
    float alpha = sum * (1.0f / 576.0f);
    g_alpha[co] = alpha;

    int S[9];
#pragma unroll
    for (int t = 0; t < 9; t++) {
        g_pw[co*9 + t] = bits[t];
        S[t] = 64 - 2*__popcll(bits[t]);   // spurious contribution of a zero padded word
    }

    // boundary classes: cls = cy*3+cx, cy/cx in {0:low edge,1:interior,2:high edge}
    for (int cls = 0; cls < 9; cls++) {
        int cy = cls / 3, cx = cls % 3;
        int corr = 0;
#pragma unroll
        for (int t = 0; t < 9; t++) {
            int ky = t / 3, kx = t % 3;
            bool oob = (cy==0 && ky==0) || (cy==2 && ky==2) ||
                       (cx==0 && kx==0) || (cx==2 && kx==2);
            if (oob) corr += S[t];
        }
        float2 c;
        c.x = alpha * (float)(576 - corr);  // base
        c.y = -2.0f * alpha;                // multiplier of popcount sum
        g_coeff[cls*COUT + co] = c;
    }
}

// ---------------------------------------------------------------------------
// Kernel 2: pack activation signs into padded u64 words; record exact zeros.
// ---------------------------------------------------------------------------
__global__ void pack_kernel(const float* __restrict__ x)
{
    int idx = blockIdx.x * blockDim.x + threadIdx.x;
    if (idx >= PADWORDS) return;
    int b  = idx / (H2*W2);
    int r  = idx % (H2*W2);
    int y2 = r / W2;
    int x2 = r % W2;
    if (y2 == 0 || y2 == H2-1 || x2 == 0 || x2 == W2-1) {
        g_packed[idx] = 0ull;
        return;
    }
    int y = y2 - 1, xx = x2 - 1;
    const float* px = x + (long long)b*CIN*HW + y*WW + xx;

    unsigned long long word = 0ull;
#pragma unroll 8
    for (int ci = 0; ci < CIN; ci++) {
        float v = px[(long long)ci*HW];
        unsigned u = __float_as_uint(v);
        unsigned treated = (u >> 31) ^ 1u;        // 1 => treated as +1
        if (!(u >> 31)) word |= (1ull << ci);
        if (v == 0.0f) {                           // sign(0)=0 in reference: needs fixup
            int slot = atomicAdd(&g_zero_count, 1);
            if (slot < ZMAX)
                g_zero_list[slot] = (b<<23) | (ci<<17) | (y<<9) | (xx<<1) | (int)treated;
        }
    }
    g_packed[idx] = word;
}

// ---------------------------------------------------------------------------
// Kernel 3: main conv. Thread = one output pixel (b,y,x); loops 64 co.
// ---------------------------------------------------------------------------
__global__ __launch_bounds__(256) void conv_kernel(float* __restrict__ out)
{
    __shared__ unsigned long long sw[COUT*9];
    __shared__ float2 scoef[9*COUT];

    for (int i = threadIdx.x; i < COUT*9; i += blockDim.x) sw[i] = g_pw[i];
    for (int i = threadIdx.x; i < 9*COUT; i += blockDim.x) scoef[i] = g_coeff[i];
    __syncthreads();

    int pix = blockIdx.x * blockDim.x + threadIdx.x;   // 0 .. 819199
    int b = pix / HW;
    int r = pix % HW;
    int y = r / WW;
    int xx = r % WW;

    // tap word for (ky,kx) lives at padded (b, y+ky, x+kx)
    const unsigned long long* pp = g_packed + ((long long)b*H2 + y)*W2 + xx;
    unsigned long long xw[9];
#pragma unroll
    for (int ky = 0; ky < 3; ky++)
#pragma unroll
        for (int kx = 0; kx < 3; kx++)
            xw[ky*3+kx] = pp[ky*W2 + kx];

    int cy = (y == 0) ? 0 : ((y == HH-1) ? 2 : 1);
    int cx = (xx == 0) ? 0 : ((xx == WW-1) ? 2 : 1);
    const float2* cf = scoef + (cy*3 + cx) * COUT;

    float* outp = out + ((long long)b*COUT)*HW + y*WW + xx;

#pragma unroll 8
    for (int co = 0; co < COUT; co++) {
        const unsigned long long* wrow = sw + co*9;
        int acc = 0;
#pragma unroll
        for (int t = 0; t < 9; t++)
            acc += __popcll(xw[t] ^ wrow[t]);
        float2 c = cf[co];
        outp[(long long)co*HW] = fmaf(c.y, (float)acc, c.x);
    }
}

// ---------------------------------------------------------------------------
// Kernel 4: fixup for exact-zero activations (sign(0)=0).
// ---------------------------------------------------------------------------
__global__ void fixup_kernel(float* __restrict__ out)
{
    int cnt = g_zero_count;
    if (cnt > ZMAX) cnt = ZMAX;
    int total = cnt * COUT * 9;
    for (int i = blockIdx.x * blockDim.x + threadIdx.x; i < total;
         i += gridDim.x * blockDim.x) {
        int zi  = i / (COUT*9);
        int rem = i % (COUT*9);
        int co  = rem / 9;
        int t   = rem % 9;
        int e   = g_zero_list[zi];
        int b   = (e >> 23) & 31;
        int ci  = (e >> 17) & 63;
        int y   = (e >> 9)  & 255;
        int xx  = (e >> 1)  & 255;
        int ts  = e & 1;               // 1 => was treated as +1
        int ky = t / 3, kx = t % 3;
        int yo = y - ky + 1;
        int xo = xx - kx + 1;
        if (yo < 0 || yo >= HH || xo < 0 || xo >= WW) continue;
        int wbit = (int)((g_pw[co*9 + t] >> ci) & 1ull);
        float ws  = wbit ? 1.0f : -1.0f;
        float tsf = ts   ? 1.0f : -1.0f;
        // we added tsf*ws*alpha; true contribution is 0 -> subtract it
        atomicAdd(&out[(((long long)b*COUT + co)*HH + yo)*WW + xo],
                  -g_alpha[co] * ws * tsf);
    }
}

// ---------------------------------------------------------------------------
extern "C" void kernel_launch(void* const* d_in, const int* in_sizes, int n_in,
                              void* d_out, int out_size)
{
    const float* x = (const float*)d_in[0];   // [32,64,160,160]
    const float* w = (const float*)d_in[1];   // [64,64,3,3]
    float* out = (float*)d_out;               // [32,64,160,160]

    prep_kernel<<<1, 64>>>(w);

    int packThreads = 256;
    int packBlocks = (PADWORDS + packThreads - 1) / packThreads;
    pack_kernel<<<packBlocks, packThreads>>>(x);

    int convBlocks = (NB*HW) / 256;           // 3200, exact
    conv_kernel<<<convBlocks, 256>>>(out);

    fixup_kernel<<<64, 256>>>(out);
}